// round 14
// baseline (speedup 1.0000x reference)
#include <cuda_runtime.h>

// OpeningLoss2D: mean((labels - grey_opening(labels, size=2))^2)
// labels: [B, C, 512, 512] fp32; out: 1 fp32 scalar.
//
// size=2 => erosion offsets [-1,0], dilation offsets [0,+1], symmetric (edge-clamp) pad.
// rmin[y] = x-pair-min of lab row y; er[y] = min(rmin[y-1], rmin[y]) (rmin[-1]=rmin[0]);
// di[y][x] = max(er[y..y+1][x..x+1]) with er[H]=er[H-1], col W-1 clamp.
//
// R9 post-mortem: smem-staged version was L1tex-bound (61.3%), DRAM only 34.9%.
// This kernel: register-rolling column walk -- NO shared memory in the main loop.
//  * thread owns one float4 column, walks 32 rows; vertical state in registers.
//  * x-neighbors via warp shuffle; lanes 0/31 use predicated 1-line L1-hit LDGs.
//  * per row/warp: ~4 LDG wavefronts + 2 edge lines + 2 SHFL (was ~12 wf + 6 LDS/STS).
//  * traffic 34/32 rows = 142 MB compulsory-ish; last-block-done reduction kept.

#define H 512
#define W 512
#define R 32                  // output rows per block
#define NBANDS (H / R)        // 16
#define W4 (W / 4)            // 128
#define NTHREADS 128
#define MAX_BLOCKS 4096

__device__ double g_partials[MAX_BLOCKS];
__device__ int    g_ticket;           // zero-init at load; self-resets each call

// Load lab row gr at this thread's column, produce:
//  v   = lab[gr][4c..4c+3]
//  rm  = rmin (x-pair-min) at cols 4c..4c+3
//  rmn = rmin at col 4c+4 (right-neighbor scalar; clamped at the right edge)
__device__ __forceinline__ void load_rmin(const float* __restrict__ base, int gr,
                                          int c4, int lane,
                                          float4& v, float4& rm, float& rmn)
{
    const float* rp = base + (size_t)gr * W;
    v = ((const float4*)rp)[c4];
    // left scalar lab[4c-1]: previous lane's v.w; lane 0 falls back to L1-hit LDG
    float lw = __shfl_up_sync(0xFFFFFFFFu, v.w, 1);
    if (lane == 0) lw = (c4 == 0) ? v.x : rp[c4 * 4 - 1];
    rm.x = fminf(lw,  v.x);
    rm.y = fminf(v.x, v.y);
    rm.z = fminf(v.y, v.z);
    rm.w = fminf(v.z, v.w);
    // right scalar lab[4c+4]: next lane's v.x; lane 31 falls back to L1-hit LDG
    float rv = __shfl_down_sync(0xFFFFFFFFu, v.x, 1);
    if (lane == 31) rv = (c4 == W4 - 1) ? v.w : rp[c4 * 4 + 4];
    // rmin at col 4c+4 = min(lab[4c+3], lab[4c+4]); right edge: rmin[W] == rmin[W-1] = rm.w
    rmn = (c4 == W4 - 1) ? rm.w : fminf(v.w, rv);
}

__global__ __launch_bounds__(NTHREADS)
void opening_loss_roll(const float* __restrict__ lab, float* __restrict__ out,
                       int nblk, double inv_n)
{
    __shared__ float  s_wsum[NTHREADS / 32];
    __shared__ int    s_islast;
    __shared__ double s_dsum[NTHREADS];

    const int img  = blockIdx.y;
    const int band = blockIdx.x;
    const int r0   = band * R;
    const float* base = lab + (size_t)img * H * W;
    const int c4   = threadIdx.x;        // 0..127, full row covered by the block
    const int lane = threadIdx.x & 31;

    // rolling state: rmin/er/lab of the previous row
    float4 rm_p; float rmn_p;
    float4 er_p; float ern_p;
    float4 lab_p;

    // prologue: rmin of row r0-1 (top clamp), then er[r0]
    {
        float4 vh, rmh; float rmnh;
        load_rmin(base, max(r0 - 1, 0), c4, lane, vh, rmh, rmnh);
        rm_p = rmh; rmn_p = rmnh;

        float4 v0, rm0; float rmn0;
        load_rmin(base, r0, c4, lane, v0, rm0, rmn0);
        er_p.x = fminf(rm_p.x, rm0.x);
        er_p.y = fminf(rm_p.y, rm0.y);
        er_p.z = fminf(rm_p.z, rm0.z);
        er_p.w = fminf(rm_p.w, rm0.w);
        ern_p  = fminf(rmn_p,  rmn0);
        rm_p = rm0; rmn_p = rmn0; lab_p = v0;
    }

    float acc = 0.f;
    // iterations y = r0+1 .. r0+R: compute er[y], emit di[y-1] (rows r0..r0+R-1)
    #pragma unroll 2
    for (int y = r0 + 1; y <= r0 + R; y++) {
        float4 er_c; float ern_c;
        float4 rm_c; float rmn_c; float4 v;
        if (y < H) {
            load_rmin(base, y, c4, lane, v, rm_c, rmn_c);
            er_c.x = fminf(rm_p.x, rm_c.x);
            er_c.y = fminf(rm_p.y, rm_c.y);
            er_c.z = fminf(rm_p.z, rm_c.z);
            er_c.w = fminf(rm_p.w, rm_c.w);
            ern_c  = fminf(rmn_p,  rmn_c);
        } else {                         // bottom clamp: er[H] == er[H-1]
            er_c = er_p; ern_c = ern_p;
            rm_c = rm_p; rmn_c = rmn_p; v = lab_p;
        }

        // di[y-1][x] = max(er[y-1][x..x+1], er[y][x..x+1])
        float t0 = fmaxf(fmaxf(er_p.x, er_p.y), fmaxf(er_c.x, er_c.y));
        float t1 = fmaxf(fmaxf(er_p.y, er_p.z), fmaxf(er_c.y, er_c.z));
        float t2 = fmaxf(fmaxf(er_p.z, er_p.w), fmaxf(er_c.z, er_c.w));
        float t3 = fmaxf(fmaxf(er_p.w, ern_p ), fmaxf(er_c.w, ern_c ));
        float d0 = lab_p.x - t0;
        float d1 = lab_p.y - t1;
        float d2 = lab_p.z - t2;
        float d3 = lab_p.w - t3;
        acc = fmaf(d0, d0, fmaf(d1, d1, fmaf(d2, d2, fmaf(d3, d3, acc))));

        er_p = er_c; ern_p = ern_c; rm_p = rm_c; rmn_p = rmn_c; lab_p = v;
    }

    // ---- Block reduction (4 warps) -> per-block double partial ----
    #pragma unroll
    for (int o = 16; o; o >>= 1)
        acc += __shfl_xor_sync(0xFFFFFFFFu, acc, o);
    const int tid = threadIdx.x;
    if (lane == 0) s_wsum[tid >> 5] = acc;
    __syncthreads();

    const int myblk = blockIdx.y * gridDim.x + blockIdx.x;
    if (tid == 0) {
        float s = s_wsum[0] + s_wsum[1] + s_wsum[2] + s_wsum[3];
        g_partials[myblk] = (double)s;
        __threadfence();
        int t = atomicAdd(&g_ticket, 1);
        s_islast = (t == nblk - 1);
    }
    __syncthreads();

    // ---- Last block: sum all partials (L2-hot) and write the scalar ----
    if (s_islast) {
        double s = 0.0;
        for (int i = tid; i < nblk; i += NTHREADS)   // fixed order -> deterministic
            s += g_partials[i];
        s_dsum[tid] = s;
        __syncthreads();
        #pragma unroll
        for (int o = NTHREADS / 2; o; o >>= 1) {
            if (tid < o) s_dsum[tid] += s_dsum[tid + o];
            __syncthreads();
        }
        if (tid == 0) {
            out[0] = (float)(s_dsum[0] * inv_n);
            g_ticket = 0;                            // reset for next graph replay
        }
    }
}

extern "C" void kernel_launch(void* const* d_in, const int* in_sizes, int n_in,
                              void* d_out, int out_size)
{
    const float* lab = (const float*)d_in[0];
    const int n      = in_sizes[0];
    const int n_img  = n / (H * W);               // 128 for [16,8,512,512]
    const int nblk   = n_img * NBANDS;            // 2048

    dim3 grid(NBANDS, n_img);
    opening_loss_roll<<<grid, NTHREADS>>>(lab, (float*)d_out, nblk, 1.0 / (double)n);
}

// round 17
// speedup vs baseline: 1.0030x; 1.0030x over previous
#include <cuda_runtime.h>

// OpeningLoss2D: mean((labels - grey_opening(labels, size=2))^2)
// labels: [B, C, 512, 512] fp32; out: 1 fp32 scalar.
//
// size=2 => erosion offsets [-1,0], dilation offsets [0,+1], symmetric (edge-clamp) pad.
// rmin[y] = x-pair-min of lab row y; er[y] = min(rmin[y-1], rmin[y]) (rmin[-1]=rmin[0]);
// di[y][x] = max(er[y..y+1][x..x+1]) with er[H]=er[H-1], col W-1 clamp.
//
// R9+R14 post-mortems: two different kernels (smem-staged L1=61%, rolling L1=14%)
// both pinned at DRAM=34.8% and ~52us => DRAM-LATENCY bound, not throughput:
// per-warp MLP~1-2, 8 eligible warps/SMSP vs ~23 needed to hide 577cyc -> 35% util.
// This kernel: FRONT-BATCHED loads -- each 8-row chunk issues 8 independent
// LDG.128s (4KB/warp in flight) before any consumption, then computes the
// rolling recurrence through the buffer. Edge scalars in compute phase (L1-hit).

#define H 512
#define W 512
#define R 32                  // output rows per block
#define CH 8                  // rows per load batch (front-batched MLP)
#define NBANDS (H / R)        // 16
#define W4 (W / 4)            // 128
#define NTHREADS 128
#define MAX_BLOCKS 4096

__device__ double g_partials[MAX_BLOCKS];
__device__ int    g_ticket;           // zero-init at load; self-resets each call

__device__ __forceinline__ float4 min4(float4 a, float4 b) {
    float4 r;
    r.x = fminf(a.x, b.x); r.y = fminf(a.y, b.y);
    r.z = fminf(a.z, b.z); r.w = fminf(a.w, b.w);
    return r;
}

// From pre-loaded v = lab[gr][4c..4c+3], produce rm = x-pair-min at cols 4c..4c+3
// and rmn = rmin at col 4c+4 (clamped at right edge). rp = row pointer (edge lanes
// re-touch neighbor scalars; lines already in L1 from the batch-load phase).
__device__ __forceinline__ void compute_rmin(const float* __restrict__ rp,
                                             int c4, int lane, float4 v,
                                             float4& rm, float& rmn)
{
    float lw = __shfl_up_sync(0xFFFFFFFFu, v.w, 1);
    if (lane == 0) lw = (c4 == 0) ? v.x : rp[c4 * 4 - 1];   // symmetric pad == clamp
    rm.x = fminf(lw,  v.x);
    rm.y = fminf(v.x, v.y);
    rm.z = fminf(v.y, v.z);
    rm.w = fminf(v.z, v.w);
    float rv = __shfl_down_sync(0xFFFFFFFFu, v.x, 1);
    if (lane == 31) rv = (c4 == W4 - 1) ? v.w : rp[c4 * 4 + 4];
    rmn = (c4 == W4 - 1) ? rm.w : fminf(v.w, rv);           // rmin[W] == rmin[W-1]
}

__global__ __launch_bounds__(NTHREADS)
void opening_loss_mlp(const float* __restrict__ lab, float* __restrict__ out,
                      int nblk, double inv_n)
{
    __shared__ float  s_wsum[NTHREADS / 32];
    __shared__ int    s_islast;
    __shared__ double s_dsum[NTHREADS];

    const int img  = blockIdx.y;
    const int band = blockIdx.x;
    const int r0   = band * R;
    const float* base = lab + (size_t)img * H * W;
    const int c4   = threadIdx.x;        // 0..127: one float4 column per thread
    const int lane = threadIdx.x & 31;

    // rolling state (previous row): rmin, er, lab
    float4 rm_p; float rmn_p;
    float4 er_p; float ern_p;
    float4 lab_p;

    // ---- prologue: rows r0-1 (top clamp) and r0, loads batched ----
    {
        const float* rp_h = base + (size_t)max(r0 - 1, 0) * W;
        const float* rp_0 = base + (size_t)r0 * W;
        float4 vh = ((const float4*)rp_h)[c4];
        float4 v0 = ((const float4*)rp_0)[c4];
        float4 rmh; float rmnh; compute_rmin(rp_h, c4, lane, vh, rmh, rmnh);
        float4 rm0; float rmn0; compute_rmin(rp_0, c4, lane, v0, rm0, rmn0);
        er_p  = min4(rmh, rm0);
        ern_p = fminf(rmnh, rmn0);
        rm_p = rm0; rmn_p = rmn0; lab_p = v0;
    }

    float acc = 0.f;
    // chunks: y = r0+1 .. r0+R, emitting di[y-1] (output rows r0..r0+R-1)
    #pragma unroll
    for (int ch = 0; ch < R / CH; ch++) {
        const int y0 = r0 + 1 + ch * CH;

        // ---- load phase: CH independent LDG.128s, no consumption ----
        float4 vb[CH];
        #pragma unroll
        for (int i = 0; i < CH; i++) {
            int gr = min(y0 + i, H - 1);          // clamp keeps last-band load in-bounds
            vb[i] = ((const float4*)(base + (size_t)gr * W))[c4];
        }

        // ---- compute phase: roll recurrence through the buffer ----
        #pragma unroll
        for (int i = 0; i < CH; i++) {
            const int y = y0 + i;
            float4 er_c; float ern_c;
            float4 rm_c; float rmn_c; float4 v;
            if (y < H) {                          // block-uniform branch
                v = vb[i];
                const float* rp = base + (size_t)y * W;
                compute_rmin(rp, c4, lane, v, rm_c, rmn_c);
                er_c  = min4(rm_p, rm_c);
                ern_c = fminf(rmn_p, rmn_c);
            } else {                              // bottom clamp: er[H] == er[H-1]
                er_c = er_p; ern_c = ern_p;
                rm_c = rm_p; rmn_c = rmn_p; v = lab_p;
            }

            // di[y-1][x] = max(er[y-1][x..x+1], er[y][x..x+1])
            float t0 = fmaxf(fmaxf(er_p.x, er_p.y), fmaxf(er_c.x, er_c.y));
            float t1 = fmaxf(fmaxf(er_p.y, er_p.z), fmaxf(er_c.y, er_c.z));
            float t2 = fmaxf(fmaxf(er_p.z, er_p.w), fmaxf(er_c.z, er_c.w));
            float t3 = fmaxf(fmaxf(er_p.w, ern_p ), fmaxf(er_c.w, ern_c ));
            float d0 = lab_p.x - t0;
            float d1 = lab_p.y - t1;
            float d2 = lab_p.z - t2;
            float d3 = lab_p.w - t3;
            acc = fmaf(d0, d0, fmaf(d1, d1, fmaf(d2, d2, fmaf(d3, d3, acc))));

            er_p = er_c; ern_p = ern_c; rm_p = rm_c; rmn_p = rmn_c; lab_p = v;
        }
    }

    // ---- Block reduction (4 warps) -> per-block double partial ----
    #pragma unroll
    for (int o = 16; o; o >>= 1)
        acc += __shfl_xor_sync(0xFFFFFFFFu, acc, o);
    const int tid = threadIdx.x;
    if (lane == 0) s_wsum[tid >> 5] = acc;
    __syncthreads();

    const int myblk = blockIdx.y * gridDim.x + blockIdx.x;
    if (tid == 0) {
        float s = s_wsum[0] + s_wsum[1] + s_wsum[2] + s_wsum[3];
        g_partials[myblk] = (double)s;
        __threadfence();
        int t = atomicAdd(&g_ticket, 1);
        s_islast = (t == nblk - 1);
    }
    __syncthreads();

    // ---- Last block: sum all partials (L2-hot) and write the scalar ----
    if (s_islast) {
        double s = 0.0;
        for (int i = tid; i < nblk; i += NTHREADS)   // fixed order -> deterministic
            s += g_partials[i];
        s_dsum[tid] = s;
        __syncthreads();
        #pragma unroll
        for (int o = NTHREADS / 2; o; o >>= 1) {
            if (tid < o) s_dsum[tid] += s_dsum[tid + o];
            __syncthreads();
        }
        if (tid == 0) {
            out[0] = (float)(s_dsum[0] * inv_n);
            g_ticket = 0;                            // reset for next graph replay
        }
    }
}

extern "C" void kernel_launch(void* const* d_in, const int* in_sizes, int n_in,
                              void* d_out, int out_size)
{
    const float* lab = (const float*)d_in[0];
    const int n      = in_sizes[0];
    const int n_img  = n / (H * W);               // 128 for [16,8,512,512]
    const int nblk   = n_img * NBANDS;            // 2048

    dim3 grid(NBANDS, n_img);
    opening_loss_mlp<<<grid, NTHREADS>>>(lab, (float*)d_out, nblk, 1.0 / (double)n);
}